// round 1
// baseline (speedup 1.0000x reference)
#include <cuda_runtime.h>
#include <cuda_bf16.h>

#define MAX_RANKS (1 << 20)

__device__ int   g_count[MAX_RANKS];
__device__ int   g_first[MAX_RANKS];
__device__ int   g_maxrank;
__device__ float g_T[256];

// ---------------------------------------------------------------- init
__global__ void k_init() {
    int stride = gridDim.x * blockDim.x;
    for (int i = blockIdx.x * blockDim.x + threadIdx.x; i < MAX_RANKS; i += stride) {
        g_count[i] = 0;
        g_first[i] = 0x7fffffff;
    }
    int t = blockIdx.x * blockDim.x + threadIdx.x;
    if (t == 0) g_maxrank = -1;
    if (t < 256) g_T[t] = 0.0f;
}

// ---------------------------------------------------------------- pass A: histogram + first index + max rank
__global__ void k_hist(const int4* __restrict__ coords, int N,
                       const int* __restrict__ Bp, const int* __restrict__ Dp,
                       const int* __restrict__ Wp) {
    int i = blockIdx.x * blockDim.x + threadIdx.x;
    int B = *Bp, D = *Dp, W = *Wp;
    int s2 = B, s1 = D * B, s0 = W * s1;
    int myrank = -1;
    if (i < N) {
        int4 c = coords[i];
        int rank = c.x * s0 + c.y * s1 + c.z * s2 + c.w;
        myrank = rank;
        atomicAdd(&g_count[rank], 1);
        atomicMin(&g_first[rank], i);
    }
    __shared__ int sm[256];
    sm[threadIdx.x] = myrank;
    __syncthreads();
    for (int off = 128; off > 0; off >>= 1) {
        if (threadIdx.x < off) sm[threadIdx.x] = max(sm[threadIdx.x], sm[threadIdx.x + off]);
        __syncthreads();
    }
    if (threadIdx.x == 0) atomicMax(&g_maxrank, sm[0]);
}

// ---------------------------------------------------------------- pass C: main per-point term  out[g] += L * feats[i]
// blockDim = (C4, 16); each block handles 16*ITER rows.
#define K2_ITER 8
__global__ void k_main(const float4* __restrict__ feats4, const int4* __restrict__ coords,
                       float4* __restrict__ out4, int N, int C4,
                       const int* __restrict__ Bp, const int* __restrict__ Dp,
                       const int* __restrict__ Hp, const int* __restrict__ Wp) {
    int tx = threadIdx.x;          // channel chunk
    int ty = threadIdx.y;          // row-in-tile
    int B = *Bp, D = *Dp, H = *Hp, W = *Wp;
    int s2 = B, s1 = D * B, s0 = W * s1;
    int maxr = g_maxrank;

    float4 tsum = make_float4(0.f, 0.f, 0.f, 0.f);

#pragma unroll
    for (int it = 0; it < K2_ITER; it++) {
        int row = (blockIdx.x * K2_ITER + it) * 16 + ty;
        if (row < N) {
            int4 c = coords[row];
            int rank = c.x * s0 + c.y * s1 + c.z * s2 + c.w;
            float4 v = feats4[(long)row * C4 + tx];
            tsum.x += v.x; tsum.y += v.y; tsum.z += v.z; tsum.w += v.w;
            if (rank != maxr) {
                float L = (float)g_count[rank];
                int g = c.x + c.y * W + c.z * H + c.w;
                float4 u = make_float4(L * v.x, L * v.y, L * v.z, L * v.w);
                atomicAdd(&out4[(long)g * C4 + tx], u);   // red.global.v4.f32
            }
        }
    }

    __shared__ float4 sm[16][64];
    sm[ty][tx] = tsum;
    __syncthreads();
    if (ty == 0) {
        float4 a = sm[0][tx];
#pragma unroll
        for (int r = 1; r < 16; r++) {
            float4 b = sm[r][tx];
            a.x += b.x; a.y += b.y; a.z += b.z; a.w += b.w;
        }
        atomicAdd((float4*)&g_T[4 * tx], a);
    }
}

// ---------------------------------------------------------------- pass B: boundary corrections, one warp per rank
__global__ void k_corr(const float4* __restrict__ feats4, float4* __restrict__ out4, int C4,
                       const int* __restrict__ Bp, const int* __restrict__ Dp,
                       const int* __restrict__ Hp, const int* __restrict__ Wp) {
    int warp = (blockIdx.x * blockDim.x + threadIdx.x) >> 5;
    int lane = threadIdx.x & 31;
    int j = warp;
    if (j >= MAX_RANKS) return;
    int Lj = g_count[j];
    if (Lj == 0) return;

    int B = *Bp, D = *Dp, H = *Hp, W = *Wp;
    int s2 = B, s1 = D * B, s0 = W * s1;

    int p = -1, Lp = 0, gj = 0, gp = 0, isLast = 0;
    if (lane == 0) {
        int c0 = j / s0; int r = j - c0 * s0;
        int c1 = r / s1; r -= c1 * s1;
        int c2 = r / s2; int c3 = r - c2 * s2;
        gj = c0 + c1 * W + c2 * H + c3;
        isLast = (j == g_maxrank);
        int q = j - 1;
        while (q >= 0 && g_count[q] == 0) q--;
        p = q;
        if (p >= 0) {
            Lp = g_count[p];
            int d0 = p / s0; int rr = p - d0 * s0;
            int d1 = rr / s1; rr -= d1 * s1;
            int d2 = rr / s2; int d3 = rr - d2 * s2;
            gp = d0 + d1 * W + d2 * H + d3;
        }
    }
    p      = __shfl_sync(0xffffffff, p, 0);
    Lp     = __shfl_sync(0xffffffff, Lp, 0);
    gj     = __shfl_sync(0xffffffff, gj, 0);
    gp     = __shfl_sync(0xffffffff, gp, 0);
    isLast = __shfl_sync(0xffffffff, isLast, 0);

    int fi = g_first[j];
    for (int x = lane; x < C4; x += 32) {
        float4 F = feats4[(long)fi * C4 + x];
        if (!isLast) {
            float nL = -(float)Lj;
            atomicAdd(&out4[(long)gj * C4 + x],
                      make_float4(nL * F.x, nL * F.y, nL * F.z, nL * F.w));
        }
        if (p >= 0) {
            float L = (float)Lp;
            atomicAdd(&out4[(long)gp * C4 + x],
                      make_float4(L * F.x, L * F.y, L * F.z, L * F.w));
        }
    }
}

// ---------------------------------------------------------------- last interval: out[g_last] += L_last * T
__global__ void k_last(float* __restrict__ out, int C,
                       const int* __restrict__ Bp, const int* __restrict__ Dp,
                       const int* __restrict__ Hp, const int* __restrict__ Wp) {
    int m = g_maxrank;
    if (m < 0) return;
    int L = g_count[m];
    int B = *Bp, D = *Dp, H = *Hp, W = *Wp;
    int s2 = B, s1 = D * B, s0 = W * s1;
    int c0 = m / s0; int r = m - c0 * s0;
    int c1 = r / s1; r -= c1 * s1;
    int c2 = r / s2; int c3 = r - c2 * s2;
    int g = c0 + c1 * W + c2 * H + c3;
    for (int c = threadIdx.x; c < C; c += blockDim.x)
        out[(long)g * C + c] += (float)L * g_T[c];
}

// ---------------------------------------------------------------- launch
extern "C" void kernel_launch(void* const* d_in, const int* in_sizes, int n_in,
                              void* d_out, int out_size) {
    const float* feats  = (const float*)d_in[0];
    const int*   coords = (const int*)d_in[1];
    const int*   Bp     = (const int*)d_in[2];
    const int*   Dp     = (const int*)d_in[3];
    const int*   Hp     = (const int*)d_in[4];
    const int*   Wp     = (const int*)d_in[5];

    int N  = in_sizes[1] / 4;
    int C  = in_sizes[0] / N;
    int C4 = C / 4;                 // C=80 -> 20 (C%4==0 for this problem)

    cudaMemsetAsync(d_out, 0, (size_t)out_size * sizeof(float), 0);
    k_init<<<2048, 512>>>();
    k_hist<<<(N + 255) / 256, 256>>>((const int4*)coords, N, Bp, Dp, Wp);

    dim3 b2(C4, 16);
    int rowsPerBlock = 16 * K2_ITER;
    k_main<<<(N + rowsPerBlock - 1) / rowsPerBlock, b2>>>(
        (const float4*)feats, (const int4*)coords, (float4*)d_out, N, C4, Bp, Dp, Hp, Wp);

    k_corr<<<MAX_RANKS / 8, 256>>>((const float4*)feats, (float4*)d_out, C4, Bp, Dp, Hp, Wp);
    k_last<<<1, 256>>>((float*)d_out, C, Bp, Dp, Hp, Wp);
}

// round 2
// speedup vs baseline: 1.2358x; 1.2358x over previous
#include <cuda_runtime.h>
#include <cuda_bf16.h>

#define MAX_RANKS (1 << 20)

__device__ int2  g_meta[MAX_RANKS];     // .x = count, .y = first index
__device__ int   g_worklist[MAX_RANKS];
__device__ int   g_wcount;
__device__ int   g_maxrank;
__device__ float g_T[256];

// ---------------------------------------------------------------- init
__global__ void k_init() {
    int stride = gridDim.x * blockDim.x;
    int t = blockIdx.x * blockDim.x + threadIdx.x;
    for (int i = t; i < MAX_RANKS; i += stride)
        g_meta[i] = make_int2(0, 0x7fffffff);
    if (t == 0) { g_maxrank = -1; g_wcount = 0; }
    if (t < 256) g_T[t] = 0.0f;
}

// ---------------------------------------------------------------- pass A: histogram + first + worklist + maxrank
__global__ void k_hist(const int4* __restrict__ coords, int N,
                       const int* __restrict__ Bp, const int* __restrict__ Dp,
                       const int* __restrict__ Wp) {
    int i = blockIdx.x * blockDim.x + threadIdx.x;
    int B = *Bp, D = *Dp, W = *Wp;
    int s2 = B, s1 = D * B, s0 = W * s1;
    int myrank = -1;
    if (i < N) {
        int4 c = coords[i];
        int rank = c.x * s0 + c.y * s1 + c.z * s2 + c.w;
        myrank = rank;
        int old = atomicAdd(&g_meta[rank].x, 1);
        if (old == 0) {
            int pos = atomicAdd(&g_wcount, 1);
            g_worklist[pos] = rank;
        }
        atomicMin(&g_meta[rank].y, i);
    }
    __shared__ int sm[256];
    sm[threadIdx.x] = myrank;
    __syncthreads();
    for (int off = 128; off > 0; off >>= 1) {
        if (threadIdx.x < off) sm[threadIdx.x] = max(sm[threadIdx.x], sm[threadIdx.x + off]);
        __syncthreads();
    }
    if (threadIdx.x == 0) atomicMax(&g_maxrank, sm[0]);
}

// ---------------------------------------------------------------- pass C: main term  out[g] += L * feats[i]
// skip last rank (handled by k_last) and skip i==first (cancels with -L*F correction)
#define K2_ITER 8
__global__ void k_main(const float4* __restrict__ feats4, const int4* __restrict__ coords,
                       float4* __restrict__ out4, int N, int C4,
                       const int* __restrict__ Bp, const int* __restrict__ Dp,
                       const int* __restrict__ Hp, const int* __restrict__ Wp) {
    int tx = threadIdx.x;          // channel chunk (0..C4-1)
    int ty = threadIdx.y;          // row-in-tile
    int B = *Bp, D = *Dp, H = *Hp, W = *Wp;
    int s2 = B, s1 = D * B, s0 = W * s1;
    int maxr = g_maxrank;

    float4 tsum = make_float4(0.f, 0.f, 0.f, 0.f);

#pragma unroll
    for (int it = 0; it < K2_ITER; it++) {
        int row = (blockIdx.x * K2_ITER + it) * 16 + ty;
        if (row < N) {
            int4 c = coords[row];
            int rank = c.x * s0 + c.y * s1 + c.z * s2 + c.w;
            float4 v = feats4[(long)row * C4 + tx];
            tsum.x += v.x; tsum.y += v.y; tsum.z += v.z; tsum.w += v.w;
            if (rank != maxr) {
                int2 m = g_meta[rank];           // broadcast load within warp
                if (row != m.y) {                // first point's term cancels
                    float L = (float)m.x;
                    int g = c.x + c.y * W + c.z * H + c.w;
                    float4 u = make_float4(L * v.x, L * v.y, L * v.z, L * v.w);
                    atomicAdd(&out4[(long)g * C4 + tx], u);   // red.global.v4.f32
                }
            }
        }
    }

    __shared__ float4 sm[16][64];
    sm[ty][tx] = tsum;
    __syncthreads();
    if (ty == 0) {
        float4 a = sm[0][tx];
#pragma unroll
        for (int r = 1; r < 16; r++) {
            float4 b = sm[r][tx];
            a.x += b.x; a.y += b.y; a.z += b.z; a.w += b.w;
        }
        atomicAdd((float4*)&g_T[4 * tx], a);
    }
}

// ---------------------------------------------------------------- pass B: each occupied rank j gives L_p * F_j to pred p
__global__ void k_corr(const float4* __restrict__ feats4, float4* __restrict__ out4, int C4,
                       const int* __restrict__ Bp, const int* __restrict__ Dp,
                       const int* __restrict__ Hp, const int* __restrict__ Wp) {
    int lane = threadIdx.x & 31;
    int warp = (blockIdx.x * blockDim.x + threadIdx.x) >> 5;
    int nwarps = (gridDim.x * blockDim.x) >> 5;

    int B = *Bp, D = *Dp, H = *Hp, W = *Wp;
    int s2 = B, s1 = D * B, s0 = W * s1;
    int nitems = g_wcount;

    for (int w = warp; w < nitems; w += nwarps) {
        int j = g_worklist[w];

        // parallel predecessor search: 32 lanes probe a coalesced window
        int p = -1;
        int base = j - 1;
        while (base >= 0) {
            int q = base - lane;
            int cnt = (q >= 0) ? g_meta[q].x : 0;
            unsigned m = __ballot_sync(0xffffffff, cnt != 0);
            if (m) { p = base - (__ffs(m) - 1); break; }
            base -= 32;
        }
        if (p < 0) continue;   // smallest rank: no predecessor

        int Lp = 0, gp = 0, fi = 0;
        if (lane == 0) {
            int2 mp = g_meta[p];
            Lp = mp.x;
            fi = g_meta[j].y;
            int d0 = p / s0; int rr = p - d0 * s0;
            int d1 = rr / s1; rr -= d1 * s1;
            int d2 = rr / s2; int d3 = rr - d2 * s2;
            gp = d0 + d1 * W + d2 * H + d3;
        }
        Lp = __shfl_sync(0xffffffff, Lp, 0);
        gp = __shfl_sync(0xffffffff, gp, 0);
        fi = __shfl_sync(0xffffffff, fi, 0);

        float L = (float)Lp;
        for (int x = lane; x < C4; x += 32) {
            float4 F = feats4[(long)fi * C4 + x];
            atomicAdd(&out4[(long)gp * C4 + x],
                      make_float4(L * F.x, L * F.y, L * F.z, L * F.w));
        }
    }
}

// ---------------------------------------------------------------- last interval: out[g_last] += L_last * T
__global__ void k_last(float* __restrict__ out, int C,
                       const int* __restrict__ Bp, const int* __restrict__ Dp,
                       const int* __restrict__ Hp, const int* __restrict__ Wp) {
    int m = g_maxrank;
    if (m < 0) return;
    int L = g_meta[m].x;
    int B = *Bp, D = *Dp, H = *Hp, W = *Wp;
    int s2 = B, s1 = D * B, s0 = W * s1;
    int c0 = m / s0; int r = m - c0 * s0;
    int c1 = r / s1; r -= c1 * s1;
    int c2 = r / s2; int c3 = r - c2 * s2;
    int g = c0 + c1 * W + c2 * H + c3;
    for (int c = threadIdx.x; c < C; c += blockDim.x)
        atomicAdd(&out[(long)g * C + c], (float)L * g_T[c]);
}

// ---------------------------------------------------------------- launch
extern "C" void kernel_launch(void* const* d_in, const int* in_sizes, int n_in,
                              void* d_out, int out_size) {
    const float* feats  = (const float*)d_in[0];
    const int*   coords = (const int*)d_in[1];
    const int*   Bp     = (const int*)d_in[2];
    const int*   Dp     = (const int*)d_in[3];
    const int*   Hp     = (const int*)d_in[4];
    const int*   Wp     = (const int*)d_in[5];

    int N  = in_sizes[1] / 4;
    int C  = in_sizes[0] / N;
    int C4 = C / 4;                 // C=80 -> 20

    cudaMemsetAsync(d_out, 0, (size_t)out_size * sizeof(float), 0);
    k_init<<<2048, 512>>>();
    k_hist<<<(N + 255) / 256, 256>>>((const int4*)coords, N, Bp, Dp, Wp);

    dim3 b2(C4, 16);
    int rowsPerBlock = 16 * K2_ITER;
    k_main<<<(N + rowsPerBlock - 1) / rowsPerBlock, b2>>>(
        (const float4*)feats, (const int4*)coords, (float4*)d_out, N, C4, Bp, Dp, Hp, Wp);

    k_corr<<<4096, 256>>>((const float4*)feats, (float4*)d_out, C4, Bp, Dp, Hp, Wp);
    k_last<<<1, 256>>>((float*)d_out, C, Bp, Dp, Hp, Wp);
}

// round 3
// speedup vs baseline: 1.6477x; 1.3332x over previous
#include <cuda_runtime.h>
#include <cuda_bf16.h>

#define MAX_RANKS (1 << 20)
#define MAX_ITEMS (1 << 20)

__device__ int2  g_meta[MAX_RANKS];     // .x = count, .y = first index
__device__ int   g_worklist[MAX_ITEMS];
__device__ int4  g_items[MAX_ITEMS];    // .x = fi, .y = gp, .z = Lp (gp=-1 -> skip)
__device__ int   g_wcount;
__device__ int   g_maxrank;
__device__ float g_T[256];

// ---------------------------------------------------------------- init
__global__ void k_init() {
    int stride = gridDim.x * blockDim.x;
    int t = blockIdx.x * blockDim.x + threadIdx.x;
    for (int i = t; i < MAX_RANKS; i += stride)
        g_meta[i] = make_int2(0, 0x7fffffff);
    if (t == 0) { g_maxrank = -1; g_wcount = 0; }
    if (t < 256) g_T[t] = 0.0f;
}

// ---------------------------------------------------------------- pass A: histogram + first + worklist + maxrank
__global__ void k_hist(const int4* __restrict__ coords, int N,
                       const int* __restrict__ Bp, const int* __restrict__ Dp,
                       const int* __restrict__ Wp) {
    int i = blockIdx.x * blockDim.x + threadIdx.x;
    int B = *Bp, D = *Dp, W = *Wp;
    int s2 = B, s1 = D * B, s0 = W * s1;
    int myrank = -1;
    if (i < N) {
        int4 c = coords[i];
        int rank = c.x * s0 + c.y * s1 + c.z * s2 + c.w;
        myrank = rank;
        int old = atomicAdd(&g_meta[rank].x, 1);
        if (old == 0) {
            int pos = atomicAdd(&g_wcount, 1);
            g_worklist[pos] = rank;
        }
        atomicMin(&g_meta[rank].y, i);
    }
    __shared__ int sm[256];
    sm[threadIdx.x] = myrank;
    __syncthreads();
    for (int off = 128; off > 0; off >>= 1) {
        if (threadIdx.x < off) sm[threadIdx.x] = max(sm[threadIdx.x], sm[threadIdx.x + off]);
        __syncthreads();
    }
    if (threadIdx.x == 0) atomicMax(&g_maxrank, sm[0]);
}

// ---------------------------------------------------------------- pass C: main term  out[g] += L * feats[i]
// skip last rank (handled by k_last) and skip i==first (cancels with -L*F correction)
#define K2_ITER 8
__global__ void k_main(const float4* __restrict__ feats4, const int4* __restrict__ coords,
                       float4* __restrict__ out4, int N, int C4,
                       const int* __restrict__ Bp, const int* __restrict__ Dp,
                       const int* __restrict__ Hp, const int* __restrict__ Wp) {
    int tx = threadIdx.x;          // channel chunk (0..C4-1)
    int ty = threadIdx.y;          // row-in-tile
    int B = *Bp, D = *Dp, H = *Hp, W = *Wp;
    int s2 = B, s1 = D * B, s0 = W * s1;
    int maxr = g_maxrank;

    float4 tsum = make_float4(0.f, 0.f, 0.f, 0.f);

#pragma unroll
    for (int it = 0; it < K2_ITER; it++) {
        int row = (blockIdx.x * K2_ITER + it) * 16 + ty;
        if (row < N) {
            int4 c = coords[row];
            int rank = c.x * s0 + c.y * s1 + c.z * s2 + c.w;
            float4 v = feats4[(long)row * C4 + tx];
            tsum.x += v.x; tsum.y += v.y; tsum.z += v.z; tsum.w += v.w;
            if (rank != maxr) {
                int2 m = g_meta[rank];
                if (row != m.y) {                // first point's term cancels
                    float L = (float)m.x;
                    int g = c.x + c.y * W + c.z * H + c.w;
                    float4 u = make_float4(L * v.x, L * v.y, L * v.z, L * v.w);
                    atomicAdd(&out4[(long)g * C4 + tx], u);   // red.global.v4.f32
                }
            }
        }
    }

    __shared__ float4 sm[16][64];
    sm[ty][tx] = tsum;
    __syncthreads();
    if (ty == 0) {
        float4 a = sm[0][tx];
#pragma unroll
        for (int r = 1; r < 16; r++) {
            float4 b = sm[r][tx];
            a.x += b.x; a.y += b.y; a.z += b.z; a.w += b.w;
        }
        atomicAdd((float4*)&g_T[4 * tx], a);
    }
}

// ---------------------------------------------------------------- prep: one THREAD per occupied rank j
// emit {fi_j, g_pred, L_pred}; the streaming apply pass consumes these.
__global__ void k_prep(const int* __restrict__ Bp, const int* __restrict__ Dp,
                       const int* __restrict__ Hp, const int* __restrict__ Wp) {
    int w = blockIdx.x * blockDim.x + threadIdx.x;
    if (w >= g_wcount) return;
    int j = g_worklist[w];

    int B = *Bp, D = *Dp, H = *Hp, W = *Wp;
    int s2 = B, s1 = D * B, s0 = W * s1;

    // serial predecessor probe (mean gap ~2.3), latency hidden by thread count
    int p = j - 1;
    int Lp = 0;
    while (p >= 0) {
        Lp = g_meta[p].x;
        if (Lp != 0) break;
        p--;
    }
    if (p < 0) { g_items[w] = make_int4(0, -1, 0, 0); return; }

    int fi = g_meta[j].y;
    int d0 = p / s0; int rr = p - d0 * s0;
    int d1 = rr / s1; rr -= d1 * s1;
    int d2 = rr / s2; int d3 = rr - d2 * s2;
    int gp = d0 + d1 * W + d2 * H + d3;
    g_items[w] = make_int4(fi, gp, Lp, 0);
}

// ---------------------------------------------------------------- apply: pure streaming gather-scale-atomic
// blockDim = (C4, 16); each block handles 16 items.
__global__ void k_apply(const float4* __restrict__ feats4, float4* __restrict__ out4, int C4) {
    int w = blockIdx.x * 16 + threadIdx.y;
    if (w >= g_wcount) return;
    int4 it = g_items[w];
    if (it.y < 0) return;
    int tx = threadIdx.x;
    float L = (float)it.z;
    float4 F = feats4[(long)it.x * C4 + tx];
    atomicAdd(&out4[(long)it.y * C4 + tx],
              make_float4(L * F.x, L * F.y, L * F.z, L * F.w));
}

// ---------------------------------------------------------------- last interval: out[g_last] += L_last * T
__global__ void k_last(float* __restrict__ out, int C,
                       const int* __restrict__ Bp, const int* __restrict__ Dp,
                       const int* __restrict__ Hp, const int* __restrict__ Wp) {
    int m = g_maxrank;
    if (m < 0) return;
    int L = g_meta[m].x;
    int B = *Bp, D = *Dp, H = *Hp, W = *Wp;
    int s2 = B, s1 = D * B, s0 = W * s1;
    int c0 = m / s0; int r = m - c0 * s0;
    int c1 = r / s1; r -= c1 * s1;
    int c2 = r / s2; int c3 = r - c2 * s2;
    int g = c0 + c1 * W + c2 * H + c3;
    for (int c = threadIdx.x; c < C; c += blockDim.x)
        atomicAdd(&out[(long)g * C + c], (float)L * g_T[c]);
}

// ---------------------------------------------------------------- launch
extern "C" void kernel_launch(void* const* d_in, const int* in_sizes, int n_in,
                              void* d_out, int out_size) {
    const float* feats  = (const float*)d_in[0];
    const int*   coords = (const int*)d_in[1];
    const int*   Bp     = (const int*)d_in[2];
    const int*   Dp     = (const int*)d_in[3];
    const int*   Hp     = (const int*)d_in[4];
    const int*   Wp     = (const int*)d_in[5];

    int N  = in_sizes[1] / 4;
    int C  = in_sizes[0] / N;
    int C4 = C / 4;                 // C=80 -> 20

    // upper bound on #occupied ranks: can't exceed N or rank space
    int maxItems = N < MAX_ITEMS ? N : MAX_ITEMS;

    cudaMemsetAsync(d_out, 0, (size_t)out_size * sizeof(float), 0);
    k_init<<<2048, 512>>>();
    k_hist<<<(N + 255) / 256, 256>>>((const int4*)coords, N, Bp, Dp, Wp);

    dim3 b2(C4, 16);
    int rowsPerBlock = 16 * K2_ITER;
    k_main<<<(N + rowsPerBlock - 1) / rowsPerBlock, b2>>>(
        (const float4*)feats, (const int4*)coords, (float4*)d_out, N, C4, Bp, Dp, Hp, Wp);

    k_prep<<<(maxItems + 255) / 256, 256>>>(Bp, Dp, Hp, Wp);

    dim3 ba(C4, 16);
    k_apply<<<(maxItems + 15) / 16, ba>>>((const float4*)feats, (float4*)d_out, C4);

    k_last<<<1, 256>>>((float*)d_out, C, Bp, Dp, Hp, Wp);
}

// round 4
// speedup vs baseline: 2.2764x; 1.3816x over previous
#include <cuda_runtime.h>
#include <cuda_bf16.h>

#define MAX_RANKS (1 << 20)

__device__ int2  g_meta[MAX_RANKS];     // .x = count, .y = first index
__device__ int2  g_pred[MAX_RANKS];     // .x = geom of predecessor (-1 none), .y = L_pred
__device__ int   g_worklist[MAX_RANKS];
__device__ int   g_wcount;
__device__ int   g_maxrank;
__device__ float g_T[256];

// ---------------------------------------------------------------- init
__global__ void k_init() {
    int stride = gridDim.x * blockDim.x;
    int t = blockIdx.x * blockDim.x + threadIdx.x;
    for (int i = t; i < MAX_RANKS; i += stride)
        g_meta[i] = make_int2(0, 0x7fffffff);
    if (t == 0) { g_maxrank = -1; g_wcount = 0; }
    if (t < 256) g_T[t] = 0.0f;
}

// ---------------------------------------------------------------- pass A: histogram + first + worklist + maxrank
__global__ void k_hist(const int4* __restrict__ coords, int N,
                       const int* __restrict__ Bp, const int* __restrict__ Dp,
                       const int* __restrict__ Wp) {
    int i = blockIdx.x * blockDim.x + threadIdx.x;
    int B = *Bp, D = *Dp, W = *Wp;
    int s2 = B, s1 = D * B, s0 = W * s1;
    int myrank = -1;
    if (i < N) {
        int4 c = __ldcs(&coords[i]);
        int rank = c.x * s0 + c.y * s1 + c.z * s2 + c.w;
        myrank = rank;
        int old = atomicAdd(&g_meta[rank].x, 1);
        if (old == 0) {
            int pos = atomicAdd(&g_wcount, 1);
            g_worklist[pos] = rank;
        }
        atomicMin(&g_meta[rank].y, i);
    }
    __shared__ int sm[256];
    sm[threadIdx.x] = myrank;
    __syncthreads();
    for (int off = 128; off > 0; off >>= 1) {
        if (threadIdx.x < off) sm[threadIdx.x] = max(sm[threadIdx.x], sm[threadIdx.x + off]);
        __syncthreads();
    }
    if (threadIdx.x == 0) atomicMax(&g_maxrank, sm[0]);
}

// ---------------------------------------------------------------- prep: one THREAD per occupied rank j
// writes g_pred[j] = {geom(pred), L(pred)} for the streaming pass.
__global__ void k_prep(const int* __restrict__ Bp, const int* __restrict__ Dp,
                       const int* __restrict__ Hp, const int* __restrict__ Wp) {
    int w = blockIdx.x * blockDim.x + threadIdx.x;
    if (w >= g_wcount) return;
    int j = g_worklist[w];

    int B = *Bp, D = *Dp, H = *Hp, W = *Wp;
    int s2 = B, s1 = D * B, s0 = W * s1;

    // serial predecessor probe (mean gap ~2.3), latency hidden by thread count
    int p = j - 1;
    int Lp = 0;
    while (p >= 0) {
        Lp = g_meta[p].x;
        if (Lp != 0) break;
        p--;
    }
    if (p < 0) { g_pred[j] = make_int2(-1, 0); return; }

    int d0 = p / s0; int rr = p - d0 * s0;
    int d1 = rr / s1; rr -= d1 * s1;
    int d2 = rr / s2; int d3 = rr - d2 * s2;
    int gp = d0 + d1 * W + d2 * H + d3;
    g_pred[j] = make_int2(gp, Lp);
}

// ---------------------------------------------------------------- main streaming pass (single feats read)
// per row i of rank k:
//   row != first, k != last : out[g_k]    += L_k   * v   (interval body)
//   row == first, pred >= 0 : out[g_pred] += L_pred* v   (F_{k} term of pred's val)
// plus block-reduced total sum T.
#define K2_ITER 8
__global__ void k_main(const float4* __restrict__ feats4, const int4* __restrict__ coords,
                       float4* __restrict__ out4, int N, int C4,
                       const int* __restrict__ Bp, const int* __restrict__ Dp,
                       const int* __restrict__ Hp, const int* __restrict__ Wp) {
    int tx = threadIdx.x;          // channel chunk (0..C4-1)
    int ty = threadIdx.y;          // row-in-tile
    int B = *Bp, D = *Dp, H = *Hp, W = *Wp;
    int s2 = B, s1 = D * B, s0 = W * s1;
    int maxr = g_maxrank;

    float4 tsum = make_float4(0.f, 0.f, 0.f, 0.f);

#pragma unroll
    for (int it = 0; it < K2_ITER; it++) {
        int row = (blockIdx.x * K2_ITER + it) * 16 + ty;
        if (row < N) {
            int4 c = __ldcs(&coords[row]);
            int rank = c.x * s0 + c.y * s1 + c.z * s2 + c.w;
            float4 v = __ldcs(&feats4[(long)row * C4 + tx]);
            tsum.x += v.x; tsum.y += v.y; tsum.z += v.z; tsum.w += v.w;
            int2 m = g_meta[rank];
            if (row == m.y) {
                int2 pr = g_pred[rank];
                if (pr.x >= 0) {
                    float L = (float)pr.y;
                    atomicAdd(&out4[(long)pr.x * C4 + tx],
                              make_float4(L * v.x, L * v.y, L * v.z, L * v.w));
                }
            } else if (rank != maxr) {
                float L = (float)m.x;
                int g = c.x + c.y * W + c.z * H + c.w;
                atomicAdd(&out4[(long)g * C4 + tx],
                          make_float4(L * v.x, L * v.y, L * v.z, L * v.w));
            }
        }
    }

    __shared__ float4 sm[16][64];
    sm[ty][tx] = tsum;
    __syncthreads();
    if (ty == 0) {
        float4 a = sm[0][tx];
#pragma unroll
        for (int r = 1; r < 16; r++) {
            float4 b = sm[r][tx];
            a.x += b.x; a.y += b.y; a.z += b.z; a.w += b.w;
        }
        atomicAdd((float4*)&g_T[4 * tx], a);
    }
}

// ---------------------------------------------------------------- last interval: out[g_last] += L_last * T
__global__ void k_last(float* __restrict__ out, int C,
                       const int* __restrict__ Bp, const int* __restrict__ Dp,
                       const int* __restrict__ Hp, const int* __restrict__ Wp) {
    int m = g_maxrank;
    if (m < 0) return;
    int L = g_meta[m].x;
    int B = *Bp, D = *Dp, H = *Hp, W = *Wp;
    int s2 = B, s1 = D * B, s0 = W * s1;
    int c0 = m / s0; int r = m - c0 * s0;
    int c1 = r / s1; r -= c1 * s1;
    int c2 = r / s2; int c3 = r - c2 * s2;
    int g = c0 + c1 * W + c2 * H + c3;
    for (int c = threadIdx.x; c < C; c += blockDim.x)
        atomicAdd(&out[(long)g * C + c], (float)L * g_T[c]);
}

// ---------------------------------------------------------------- launch
extern "C" void kernel_launch(void* const* d_in, const int* in_sizes, int n_in,
                              void* d_out, int out_size) {
    const float* feats  = (const float*)d_in[0];
    const int*   coords = (const int*)d_in[1];
    const int*   Bp     = (const int*)d_in[2];
    const int*   Dp     = (const int*)d_in[3];
    const int*   Hp     = (const int*)d_in[4];
    const int*   Wp     = (const int*)d_in[5];

    int N  = in_sizes[1] / 4;
    int C  = in_sizes[0] / N;
    int C4 = C / 4;                 // C=80 -> 20

    int maxItems = N < MAX_RANKS ? N : MAX_RANKS;

    cudaMemsetAsync(d_out, 0, (size_t)out_size * sizeof(float), 0);
    k_init<<<2048, 512>>>();
    k_hist<<<(N + 255) / 256, 256>>>((const int4*)coords, N, Bp, Dp, Wp);
    k_prep<<<(maxItems + 255) / 256, 256>>>(Bp, Dp, Hp, Wp);

    dim3 b2(C4, 16);
    int rowsPerBlock = 16 * K2_ITER;
    k_main<<<(N + rowsPerBlock - 1) / rowsPerBlock, b2>>>(
        (const float4*)feats, (const int4*)coords, (float4*)d_out, N, C4, Bp, Dp, Hp, Wp);

    k_last<<<1, 256>>>((float*)d_out, C, Bp, Dp, Hp, Wp);
}